// round 14
// baseline (speedup 1.0000x reference)
#include <cuda_runtime.h>

// FeatureContraction: out[b,c,w,x,v] = sum_i x[b,c,w,x,v,i] * attr[b,c,i]
// x: [16384, 768, 16] f32, attr: [16384, 16] f32, out: [16384, 768] f32.
// Pure one-pass stream: 855 MB compulsory traffic. FINAL KERNEL (converged).
//
// Session history (13 rounds, single-variable experiments):
// R1:  float4 loads, 1 bc/CTA    -> 127.2 us @ 86% DRAM.
// R2:  8 bc/CTA SERIAL loop      -> 141.4 us (REGRESSION: dependency bubbles).
// R3:  +ldcs/stcs hints          -> 127.0 us (NEUTRAL).
// R4:  LDG.256 (v8.f32)          -> 124.8 us @ 87.6% DRAM, L1 71->43%.
// R5:  hoist x loads over BAR    -> 124.8 us (kernel 122.3us; occ-invariant).
// R6:  no smem/BAR @256thr       -> 124.9 us (NEUTRAL).
// R7:  4 out/thr + STG.128       -> 133.6 us (REGRESSION: regalloc killed MLP).
// R8:  R5 confirmed              -> 124.77 us, 7009 GB/s.
// R9:  PARALLEL 2-bc, 512 thr    -> 123.68 us (WIN).
// R10: PARALLEL 4-bc, 1024 thr   -> 125.66 us (REGRESSION: whole-SM BAR coupling).
// R11: R9 minus smem/BAR         -> 125.41 us (REGRESSION: regs 62->40, load
//      front-batch serialized; the BAR pins 48 load regs live).
// R12: R9 reconfirmed            -> 123.62 us, kernel 121.57us, 7027 GB/s.
// R13: stability check           -> 123.39 us, kernel 121.8us, 7015 GB/s.
//      R9/R12/R13 spread = 0.3 us -> measuring noise, not structure.
//
// MODEL (all 13 points): t == 855 MB / ~7.0 TB/s (B300 path-independent
// LTS/DRAM streaming cap) iff the per-thread 6x LDG.256 front-batch survives
// register allocation (regs=62). Non-binding: occupancy 37-62%, cache hints,
// store width, barrier presence, CTA count 4k-16k. Deeper MLP rejected:
// in-flight bytes/SM unchanged (regs ~116 halves resident threads), only
// re-exposes the R7/R11 regalloc-serialization failure. Residual ~12% of
// HBM spec = DRAM r/w turnaround on a 16:1 mixed stream; not SASS-reachable.

#define BC_TOTAL   16384      // B*C
#define WXV        768        // X*Y*Y = 3*16*16
#define BC_PER_BLK 2
#define THREADS    (256 * BC_PER_BLK)       // 512
#define PER_THR    3                         // outputs per thread
#define GRID       (BC_TOTAL / BC_PER_BLK)   // 8192

__device__ __forceinline__ void ldg256(const float* __restrict__ p,
                                       float4& lo, float4& hi)
{
    asm("ld.global.v8.f32 {%0,%1,%2,%3,%4,%5,%6,%7}, [%8];"
        : "=f"(lo.x), "=f"(lo.y), "=f"(lo.z), "=f"(lo.w),
          "=f"(hi.x), "=f"(hi.y), "=f"(hi.z), "=f"(hi.w)
        : "l"(p));
}

__global__ __launch_bounds__(THREADS)
void feature_contraction_kernel(const float* __restrict__ x,
                                const float4* __restrict__ attr,
                                float* __restrict__ out)
{
    // Threads [0,256) handle bc0, threads [256,512) handle bc0+1.
    const int sub  = threadIdx.x >> 8;          // 0 or 1
    const int tid  = threadIdx.x & 255;         // 0..255 within sub-block
    const int bc   = blockIdx.x * BC_PER_BLK + sub;

    const float* __restrict__ xb = x + (size_t)bc * WXV * 16;

    // ---- Phase 1: issue all 6 independent LDG.256 first (48-reg
    // front-batch; nothing blocks them). ----
    float4 v[PER_THR][4];
    int    o[PER_THR];

#pragma unroll
    for (int k = 0; k < PER_THR; k++) {
        o[k] = k * 256 + tid;
        const float* __restrict__ xp = xb + (size_t)o[k] * 16;
        ldg256(xp,     v[k][0], v[k][1]);
        ldg256(xp + 8, v[k][2], v[k][3]);
    }

    // ---- Phase 2: stage both bc's attr vectors through smem, overlapped
    // with the x loads in flight. The BAR doubles as the scheduling fence
    // that keeps the 48 load-dest registers live (regs=62) — removing it
    // (R11) lets ptxas serialize the load batch and costs ~2 us. ----
    __shared__ float4 s_a[BC_PER_BLK][4];
    if (threadIdx.x < 4 * BC_PER_BLK) {
        const int j = threadIdx.x >> 2;          // which bc
        const int q = threadIdx.x & 3;           // which float4
        s_a[j][q] = attr[((size_t)blockIdx.x * BC_PER_BLK + j) * 4 + q];
    }
    __syncthreads();

    const float4 a0 = s_a[sub][0];
    const float4 a1 = s_a[sub][1];
    const float4 a2 = s_a[sub][2];
    const float4 a3 = s_a[sub][3];

    // ---- Phase 3: FMA + store. ----
#pragma unroll
    for (int k = 0; k < PER_THR; k++) {
        float s;
        s  = v[k][0].x * a0.x;
        s += v[k][0].y * a0.y;
        s += v[k][0].z * a0.z;
        s += v[k][0].w * a0.w;
        s += v[k][1].x * a1.x;
        s += v[k][1].y * a1.y;
        s += v[k][1].z * a1.z;
        s += v[k][1].w * a1.w;
        s += v[k][2].x * a2.x;
        s += v[k][2].y * a2.y;
        s += v[k][2].z * a2.z;
        s += v[k][2].w * a2.w;
        s += v[k][3].x * a3.x;
        s += v[k][3].y * a3.y;
        s += v[k][3].z * a3.z;
        s += v[k][3].w * a3.w;
        out[(size_t)bc * WXV + o[k]] = s;
    }
}

extern "C" void kernel_launch(void* const* d_in, const int* in_sizes, int n_in,
                              void* d_out, int out_size)
{
    const float*  x    = (const float*)d_in[0];
    const float4* attr = (const float4*)d_in[1];
    float*        out  = (float*)d_out;

    feature_contraction_kernel<<<GRID, THREADS>>>(x, attr, out);
}

// round 15
// speedup vs baseline: 1.0029x; 1.0029x over previous
#include <cuda_runtime.h>

// FeatureContraction: out[b,c,w,x,v] = sum_i x[b,c,w,x,v,i] * attr[b,c,i]
// x: [16384, 768, 16] f32, attr: [16384, 16] f32, out: [16384, 768] f32.
// Pure one-pass stream: 855 MB compulsory traffic. FINAL KERNEL (converged,
// confirmed 4x: 123.68 / 123.62 / 123.39 / 123.65 us; sigma ~0.13 us).
//
// Session history (14 rounds, single-variable experiments):
// R1:  float4 loads, 1 bc/CTA    -> 127.2 us @ 86% DRAM.
// R2:  8 bc/CTA SERIAL loop      -> 141.4 us (REGRESSION: dependency bubbles).
// R3:  +ldcs/stcs hints          -> 127.0 us (NEUTRAL).
// R4:  LDG.256 (v8.f32)          -> 124.8 us @ 87.6% DRAM, L1 71->43%.
// R5:  hoist x loads over BAR    -> 124.8 us (kernel 122.3us; occ-invariant).
// R6:  no smem/BAR @256thr       -> 124.9 us (NEUTRAL).
// R7:  4 out/thr + STG.128       -> 133.6 us (REGRESSION: regalloc killed MLP).
// R8:  R5 confirmed              -> 124.77 us, 7009 GB/s.
// R9:  PARALLEL 2-bc, 512 thr    -> 123.68 us (WIN).
// R10: PARALLEL 4-bc, 1024 thr   -> 125.66 us (REGRESSION: whole-SM BAR coupling).
// R11: R9 minus smem/BAR         -> 125.41 us (REGRESSION: regs 62->40, load
//      front-batch serialized; the BAR pins 48 load regs live).
// R12-R14: optimum reconfirmed   -> 123.62 / 123.39 / 123.65 us,
//      kernel 121.4-121.8 us, 7015-7040 GB/s, DRAM 88.5-88.8%.
//
// MODEL (all 14 points): t == 855 MB / ~7.0 TB/s (B300 path-independent
// LTS/DRAM streaming cap) iff the per-thread 6x LDG.256 front-batch survives
// register allocation (regs=62, BAR-fenced). Non-binding: occupancy 37-62%,
// cache hints, store width, barrier presence, CTA count 4k-16k. Rejected on
// accounting: deeper MLP (in-flight bytes/SM invariant), TMA (path-indep cap),
// write batching (turnaround is chip-global), wave rebalance (<0.4%).
// Residual ~12% of HBM spec = DRAM r/w turnaround on a 16:1 mixed stream.

#define BC_TOTAL   16384      // B*C
#define WXV        768        // X*Y*Y = 3*16*16
#define BC_PER_BLK 2
#define THREADS    (256 * BC_PER_BLK)       // 512
#define PER_THR    3                         // outputs per thread
#define GRID       (BC_TOTAL / BC_PER_BLK)   // 8192

__device__ __forceinline__ void ldg256(const float* __restrict__ p,
                                       float4& lo, float4& hi)
{
    asm("ld.global.v8.f32 {%0,%1,%2,%3,%4,%5,%6,%7}, [%8];"
        : "=f"(lo.x), "=f"(lo.y), "=f"(lo.z), "=f"(lo.w),
          "=f"(hi.x), "=f"(hi.y), "=f"(hi.z), "=f"(hi.w)
        : "l"(p));
}

__global__ __launch_bounds__(THREADS)
void feature_contraction_kernel(const float* __restrict__ x,
                                const float4* __restrict__ attr,
                                float* __restrict__ out)
{
    // Threads [0,256) handle bc0, threads [256,512) handle bc0+1.
    const int sub  = threadIdx.x >> 8;          // 0 or 1
    const int tid  = threadIdx.x & 255;         // 0..255 within sub-block
    const int bc   = blockIdx.x * BC_PER_BLK + sub;

    const float* __restrict__ xb = x + (size_t)bc * WXV * 16;

    // ---- Phase 1: issue all 6 independent LDG.256 first (48-reg
    // front-batch; nothing blocks them). ----
    float4 v[PER_THR][4];
    int    o[PER_THR];

#pragma unroll
    for (int k = 0; k < PER_THR; k++) {
        o[k] = k * 256 + tid;
        const float* __restrict__ xp = xb + (size_t)o[k] * 16;
        ldg256(xp,     v[k][0], v[k][1]);
        ldg256(xp + 8, v[k][2], v[k][3]);
    }

    // ---- Phase 2: stage both bc's attr vectors through smem, overlapped
    // with the x loads in flight. The BAR doubles as the scheduling fence
    // that keeps the 48 load-dest registers live (regs=62) — removing it
    // (R11) lets ptxas serialize the load batch and costs ~2 us. ----
    __shared__ float4 s_a[BC_PER_BLK][4];
    if (threadIdx.x < 4 * BC_PER_BLK) {
        const int j = threadIdx.x >> 2;          // which bc
        const int q = threadIdx.x & 3;           // which float4
        s_a[j][q] = attr[((size_t)blockIdx.x * BC_PER_BLK + j) * 4 + q];
    }
    __syncthreads();

    const float4 a0 = s_a[sub][0];
    const float4 a1 = s_a[sub][1];
    const float4 a2 = s_a[sub][2];
    const float4 a3 = s_a[sub][3];

    // ---- Phase 3: FMA + store. ----
#pragma unroll
    for (int k = 0; k < PER_THR; k++) {
        float s;
        s  = v[k][0].x * a0.x;
        s += v[k][0].y * a0.y;
        s += v[k][0].z * a0.z;
        s += v[k][0].w * a0.w;
        s += v[k][1].x * a1.x;
        s += v[k][1].y * a1.y;
        s += v[k][1].z * a1.z;
        s += v[k][1].w * a1.w;
        s += v[k][2].x * a2.x;
        s += v[k][2].y * a2.y;
        s += v[k][2].z * a2.z;
        s += v[k][2].w * a2.w;
        s += v[k][3].x * a3.x;
        s += v[k][3].y * a3.y;
        s += v[k][3].z * a3.z;
        s += v[k][3].w * a3.w;
        out[(size_t)bc * WXV + o[k]] = s;
    }
}

extern "C" void kernel_launch(void* const* d_in, const int* in_sizes, int n_in,
                              void* d_out, int out_size)
{
    const float*  x    = (const float*)d_in[0];
    const float4* attr = (const float4*)d_in[1];
    float*        out  = (float*)d_out;

    feature_contraction_kernel<<<GRID, THREADS>>>(x, attr, out);
}